// round 2
// baseline (speedup 1.0000x reference)
#include <cuda_runtime.h>
#include <cuda_bf16.h>

#define LOOP 100
#define BN_EPS 1e-5f

// MUFU-based approximations (sqrt.approx handles 0 -> 0 correctly)
__device__ __forceinline__ float ex2_approx(float x) {
    float y; asm("ex2.approx.f32 %0, %1;" : "=f"(y) : "f"(x)); return y;
}
__device__ __forceinline__ float rcp_approx(float x) {
    float y; asm("rcp.approx.f32 %0, %1;" : "=f"(y) : "f"(x)); return y;
}
__device__ __forceinline__ float sqrt_approx(float x) {
    float y; asm("sqrt.approx.f32 %0, %1;" : "=f"(y) : "f"(x)); return y;
}
__device__ __forceinline__ float fast_sigmoid(float a) {
    // 1 / (1 + exp(-a)) = 1 / (1 + 2^(-a*log2(e)))
    return rcp_approx(1.0f + ex2_approx(-a * 1.4426950408889634f));
}

__global__ void __launch_bounds__(256, 1)
model_fused_kernel(const float* __restrict__ x,
                   const float* __restrict__ conv_w,
                   const float* __restrict__ conv_b,
                   const float* __restrict__ bn_gamma,
                   const float* __restrict__ bn_beta,
                   const float* __restrict__ bn_mean,
                   const float* __restrict__ bn_var,
                   const float* __restrict__ w1,
                   const float* __restrict__ b1,
                   const float* __restrict__ w2,
                   const float* __restrict__ b2,
                   const float* __restrict__ w3,
                   const float* __restrict__ b3,
                   float* __restrict__ out)
{
    // kk stores the 1600-element flattened history exactly in jax flatten order:
    // kk[t*16 + p], so feats[i][j] = kk[i*100 + j] after the double reshape.
    __shared__ float kk[LOOP * 16];     // 6400 B
    __shared__ float w1s[60 * 100];     // 24000 B
    __shared__ float b1s[60];
    __shared__ float w2s[16 * 60];      // 3840 B
    __shared__ float b2s[16];
    __shared__ float w3s[8 * 16];
    __shared__ float b3s[8];
    __shared__ float h1n[16 * 60];      // 3840 B
    __shared__ float h2s[16 * 16];      // 1024 B

    const int tid = threadIdx.x;

    if (tid < 16) {
        // ---------------- Phase 1: serial conv recurrence (warp 0, lanes 0-15) ----
        const int r = tid >> 2;
        const int c = tid & 3;

        float w[9];
        #pragma unroll
        for (int k = 0; k < 9; k++) w[k] = conv_w[k];
        const float cb = conv_b[0];
        const float inv_std = bn_gamma[0] * rsqrtf(bn_var[0] + BN_EPS);
        const float shift   = bn_beta[0] - bn_mean[0] * inv_std;

        float v = x[tid];

        #pragma unroll 4
        for (int t = 0; t < LOOP; t++) {
            float a = cb;
            #pragma unroll
            for (int dr = 0; dr < 3; dr++) {
                #pragma unroll
                for (int dc = 0; dc < 3; dc++) {
                    const int nr = r + dr - 1;
                    const int nc = c + dc - 1;
                    int sl = tid + (dr - 1) * 4 + (dc - 1);
                    sl = max(0, min(15, sl));                     // keep src lane in mask
                    const float nv = __shfl_sync(0x0000FFFFu, v, sl);
                    const bool ok = ((unsigned)nr < 4u) && ((unsigned)nc < 4u);
                    a = fmaf(w[dr * 3 + dc], ok ? nv : 0.0f, a);
                }
            }
            const float sw = a * fast_sigmoid(a);
            const float b  = fmaf(sw, inv_std, shift);   // swish(a)*inv_std + shift
            const float h  = a * b;
            const float xn = copysignf(sqrt_approx(fabsf(h)), h);
            kk[t * 16 + tid] = xn;
            v = xn;
        }
    } else if (tid >= 32) {
        // ---------------- Overlapped weight prefetch (warps 1-7) ------------------
        const int pt = tid - 32;             // 0..223
        const int NP = 224;
        for (int i = pt; i < 6000; i += NP) w1s[i] = w1[i];
        for (int i = pt; i < 960;  i += NP) w2s[i] = w2[i];
        for (int i = pt; i < 128;  i += NP) w3s[i] = w3[i];
        for (int i = pt; i < 60;   i += NP) b1s[i] = b1[i];
        if (pt < 16) b2s[pt] = b2[pt];
        if (pt < 8)  b3s[pt] = b3[pt];
    }
    __syncthreads();

    // ---------------- Phase 2: h1 = 2*swish(feats @ w1.T + b1) - 1 ----------------
    // 960 outputs, dot length 100
    for (int idx = tid; idx < 16 * 60; idx += 256) {
        const int i = idx / 60;
        const int o = idx % 60;
        const float* f  = &kk[i * 100];
        const float* wr = &w1s[o * 100];
        float a0 = 0.f, a1 = 0.f, a2 = 0.f, a3 = 0.f;
        #pragma unroll
        for (int j = 0; j < 100; j += 4) {
            a0 = fmaf(f[j + 0], wr[j + 0], a0);
            a1 = fmaf(f[j + 1], wr[j + 1], a1);
            a2 = fmaf(f[j + 2], wr[j + 2], a2);
            a3 = fmaf(f[j + 3], wr[j + 3], a3);
        }
        const float hv = (a0 + a1) + (a2 + a3) + b1s[o];
        const float sw = hv * fast_sigmoid(hv);
        h1n[idx] = 2.0f * sw - 1.0f;        // (swish - 0.5)/0.5
    }
    __syncthreads();

    // ---------------- Phase 3: h2 = swish(h1n @ w2.T + b2) ------------------------
    // 256 outputs, dot length 60
    if (tid < 256) {
        const int i = tid >> 4;
        const int o = tid & 15;
        const float* f  = &h1n[i * 60];
        const float* wr = &w2s[o * 60];
        float acc = 0.f;
        #pragma unroll
        for (int j = 0; j < 60; j++) acc = fmaf(f[j], wr[j], acc);
        acc += b2s[o];
        h2s[tid] = acc * fast_sigmoid(acc);
    }
    __syncthreads();

    // ---------------- Phase 4: y = h2 @ w3.T + b3 ---------------------------------
    // 128 outputs, dot length 16
    if (tid < 128) {
        const int i = tid >> 3;
        const int o = tid & 7;
        const float* f  = &h2s[i * 16];
        const float* wr = &w3s[o * 16];
        float acc = 0.f;
        #pragma unroll
        for (int j = 0; j < 16; j++) acc = fmaf(f[j], wr[j], acc);
        out[tid] = acc + b3s[o];
    }
}

extern "C" void kernel_launch(void* const* d_in, const int* in_sizes, int n_in,
                              void* d_out, int out_size)
{
    const float* x        = (const float*)d_in[0];
    const float* conv_w   = (const float*)d_in[1];
    const float* conv_b   = (const float*)d_in[2];
    const float* bn_gamma = (const float*)d_in[3];
    const float* bn_beta  = (const float*)d_in[4];
    const float* bn_mean  = (const float*)d_in[5];
    const float* bn_var   = (const float*)d_in[6];
    const float* w1       = (const float*)d_in[7];
    const float* b1       = (const float*)d_in[8];
    const float* w2       = (const float*)d_in[9];
    const float* b2       = (const float*)d_in[10];
    const float* w3       = (const float*)d_in[11];
    const float* b3       = (const float*)d_in[12];
    float* out = (float*)d_out;

    model_fused_kernel<<<1, 256>>>(x, conv_w, conv_b, bn_gamma, bn_beta,
                                   bn_mean, bn_var, w1, b1, w2, b2, w3, b3, out);
}

// round 3
// speedup vs baseline: 1.4726x; 1.4726x over previous
#include <cuda_runtime.h>
#include <cuda_bf16.h>

#define LOOP 100
#define BN_EPS 1e-5f

__device__ __forceinline__ float ex2_approx(float x) {
    float y; asm("ex2.approx.f32 %0, %1;" : "=f"(y) : "f"(x)); return y;
}
__device__ __forceinline__ float rcp_approx(float x) {
    float y; asm("rcp.approx.f32 %0, %1;" : "=f"(y) : "f"(x)); return y;
}
__device__ __forceinline__ float tanh_approx(float x) {
    float y; asm("tanh.approx.f32 %0, %1;" : "=f"(y) : "f"(x)); return y;
}
__device__ __forceinline__ float rsqrt_approx(float x) {
    float y; asm("rsqrt.approx.f32 %0, %1;" : "=f"(y) : "f"(x)); return y;
}
__device__ __forceinline__ float fast_sigmoid(float a) {
    // accurate path for the MLP (not on the serial critical chain)
    return rcp_approx(1.0f + ex2_approx(-a * 1.4426950408889634f));
}

__global__ void __launch_bounds__(256, 1)
model_fused_kernel(const float* __restrict__ x,
                   const float* __restrict__ conv_w,
                   const float* __restrict__ conv_b,
                   const float* __restrict__ bn_gamma,
                   const float* __restrict__ bn_beta,
                   const float* __restrict__ bn_mean,
                   const float* __restrict__ bn_var,
                   const float* __restrict__ w1,
                   const float* __restrict__ b1,
                   const float* __restrict__ w2,
                   const float* __restrict__ b2,
                   const float* __restrict__ w3,
                   const float* __restrict__ b3,
                   float* __restrict__ out)
{
    // kk is the flat history: kk[t*16+p]. Because feats[i][j] = kk_flat[i*100+j],
    // phase 2 simply reads contiguous rows of 100 from this flat array.
    __shared__ __align__(16) float kk[LOOP * 16];     // 6400 B
    __shared__ __align__(16) float w1s[60 * 100];     // 24000 B
    __shared__ __align__(16) float w2s[16 * 60];
    __shared__ __align__(16) float w3s[8 * 16];
    __shared__ __align__(16) float h1n[16 * 60];
    __shared__ __align__(16) float h2s[16 * 16];
    __shared__ float b1s[60];
    __shared__ float b2s[16];
    __shared__ float b3s[8];

    const int tid = threadIdx.x;

    if (tid < 16) {
        // ======== Phase 1: serial conv recurrence (warp 0, lanes 0-15) ========
        const int r = tid >> 2;
        const int c = tid & 3;

        // Hoisted: boundary-masked weights + shuffle source lanes
        float wm[9];
        int   ln[9];
        #pragma unroll
        for (int dr = 0; dr < 3; dr++) {
            #pragma unroll
            for (int dc = 0; dc < 3; dc++) {
                const int nr = r + dr - 1;
                const int nc = c + dc - 1;
                const bool ok = ((unsigned)nr < 4u) && ((unsigned)nc < 4u);
                const int k = dr * 3 + dc;
                wm[k] = ok ? conv_w[k] : 0.0f;
                ln[k] = ok ? (nr * 4 + nc) : tid;
            }
        }
        const float cb      = conv_b[0];
        const float inv_std = bn_gamma[0] * rsqrtf(bn_var[0] + BN_EPS);
        const float shift   = bn_beta[0] - bn_mean[0] * inv_std;
        const float c1      = 0.5f * inv_std;

        float v = x[tid];

        #pragma unroll 5
        for (int t = 0; t < LOOP; t++) {
            // neighbor gather: 8 independent shuffles (center = v)
            const float n0 = __shfl_sync(0x0000FFFFu, v, ln[0]);
            const float n1 = __shfl_sync(0x0000FFFFu, v, ln[1]);
            const float n2 = __shfl_sync(0x0000FFFFu, v, ln[2]);
            const float n3 = __shfl_sync(0x0000FFFFu, v, ln[3]);
            const float n5 = __shfl_sync(0x0000FFFFu, v, ln[5]);
            const float n6 = __shfl_sync(0x0000FFFFu, v, ln[6]);
            const float n7 = __shfl_sync(0x0000FFFFu, v, ln[7]);
            const float n8 = __shfl_sync(0x0000FFFFu, v, ln[8]);

            // conv: 3 parallel FMA chains (depth 12) + 2 adds
            const float a0 = fmaf(wm[0], n0, fmaf(wm[3], n3, fmaf(wm[6], n6, cb)));
            const float a1 = fmaf(wm[1], n1, fmaf(wm[4], v,  wm[7] * n7));
            const float a2 = fmaf(wm[2], n2, fmaf(wm[5], n5, wm[8] * n8));
            const float a  = (a0 + a1) + a2;

            // h = a^2*inv_std*sigmoid(a) + a*shift, with sigmoid = 0.5 + 0.5*tanh(a/2):
            //   h = p2*tanh(a/2) + (p2 + a*shift),  p2 = 0.5*inv_std*a^2
            const float th = tanh_approx(0.5f * a);
            const float t1 = a * c1;
            const float p2 = a * t1;
            const float pq = fmaf(a, shift, p2);
            const float h  = fmaf(p2, th, pq);

            // xn = sign(h)*sqrt(|h|) = h * rsqrt(|h| + eps)   (exact 0 at h==0)
            const float ah = fabsf(h) + 1e-30f;
            const float xn = h * rsqrt_approx(ah);

            kk[t * 16 + tid] = xn;
            v = xn;
        }
    } else if (tid >= 32) {
        // ======== Overlapped weight prefetch (warps 1-7, hidden by phase 1) ====
        const int pt = tid - 32;             // 0..223
        const int NP = 224;
        for (int i = pt; i < 6000; i += NP) w1s[i] = w1[i];
        for (int i = pt; i < 960;  i += NP) w2s[i] = w2[i];
        for (int i = pt; i < 128;  i += NP) w3s[i] = w3[i];
        for (int i = pt; i < 60;   i += NP) b1s[i] = b1[i];
        if (pt < 16) b2s[pt] = b2[pt];
        if (pt < 8)  b3s[pt] = b3[pt];
    }
    __syncthreads();

    const int warp = tid >> 5;
    const int lane = tid & 31;
    const int i    = lane & 15;          // batch row 0..15
    const int sub  = lane >> 4;          // output-column select within warp

    // ======== Phase 2: h1 = 2*swish(feats @ w1.T + b1) - 1 =================
    // Half-warp scheme: weight float4 is half-warp-uniform (broadcast),
    // feature reads at stride 100 are bank-conflict-free.
    #pragma unroll
    for (int pass = 0; pass < 4; pass++) {
        const int o = 2 * (warp + 8 * pass) + sub;   // 0..63
        if (o < 60) {
            const float4* f4 = (const float4*)&kk[i * 100];
            const float4* g4 = (const float4*)&w1s[o * 100];
            float a0 = 0.f, a1 = 0.f, a2 = 0.f, a3 = 0.f;
            #pragma unroll
            for (int j = 0; j < 25; j++) {
                const float4 f = f4[j];
                const float4 g = g4[j];
                a0 = fmaf(f.x, g.x, a0);
                a1 = fmaf(f.y, g.y, a1);
                a2 = fmaf(f.z, g.z, a2);
                a3 = fmaf(f.w, g.w, a3);
            }
            const float hv = (a0 + a1) + (a2 + a3) + b1s[o];
            const float sw = hv * fast_sigmoid(hv);
            h1n[i * 60 + o] = 2.0f * sw - 1.0f;
        }
    }
    __syncthreads();

    // ======== Phase 3: h2 = swish(h1n @ w2.T + b2), 16x16 in one pass ======
    {
        const int o = 2 * warp + sub;                // 0..15
        const float4* f4 = (const float4*)&h1n[i * 60];
        const float4* g4 = (const float4*)&w2s[o * 60];
        float a0 = 0.f, a1 = 0.f, a2 = 0.f, a3 = 0.f;
        #pragma unroll
        for (int j = 0; j < 15; j++) {
            const float4 f = f4[j];
            const float4 g = g4[j];
            a0 = fmaf(f.x, g.x, a0);
            a1 = fmaf(f.y, g.y, a1);
            a2 = fmaf(f.z, g.z, a2);
            a3 = fmaf(f.w, g.w, a3);
        }
        const float hv = (a0 + a1) + (a2 + a3) + b2s[o];
        h2s[i * 16 + o] = hv * fast_sigmoid(hv);
    }
    __syncthreads();

    // ======== Phase 4: y = h2 @ w3.T + b3 (128 outputs) ====================
    if (tid < 128) {
        const int ii = tid >> 3;
        const int o  = tid & 7;
        const float4* f4 = (const float4*)&h2s[ii * 16];
        const float4* g4 = (const float4*)&w3s[o * 16];
        float acc = 0.f;
        #pragma unroll
        for (int j = 0; j < 4; j++) {
            const float4 f = f4[j];
            const float4 g = g4[j];
            acc = fmaf(f.x, g.x, acc);
            acc = fmaf(f.y, g.y, acc);
            acc = fmaf(f.z, g.z, acc);
            acc = fmaf(f.w, g.w, acc);
        }
        out[tid] = acc + b3s[o];
    }
}

extern "C" void kernel_launch(void* const* d_in, const int* in_sizes, int n_in,
                              void* d_out, int out_size)
{
    const float* x        = (const float*)d_in[0];
    const float* conv_w   = (const float*)d_in[1];
    const float* conv_b   = (const float*)d_in[2];
    const float* bn_gamma = (const float*)d_in[3];
    const float* bn_beta  = (const float*)d_in[4];
    const float* bn_mean  = (const float*)d_in[5];
    const float* bn_var   = (const float*)d_in[6];
    const float* w1       = (const float*)d_in[7];
    const float* b1       = (const float*)d_in[8];
    const float* w2       = (const float*)d_in[9];
    const float* b2       = (const float*)d_in[10];
    const float* w3       = (const float*)d_in[11];
    const float* b3       = (const float*)d_in[12];
    float* out = (float*)d_out;

    model_fused_kernel<<<1, 256>>>(x, conv_w, conv_b, bn_gamma, bn_beta,
                                   bn_mean, bn_var, w1, b1, w2, b2, w3, b3, out);
}